// round 12
// baseline (speedup 1.0000x reference)
#include <cuda_runtime.h>
#include <cstdint>
#include <math.h>

#define T_SEQ    2048
#define B_BATCH  2
#define DM       1024
#define NHEAD    16
#define HDIM     64
#define ROWS     (B_BATCH * T_SEQ)      // 4096
#define QKV_COLS (3 * DM)               // 3072

// Scratch (allocation-guard compliant: device globals)
__device__ float g_attn[(size_t)ROWS * DM];          // 16 MB (tf32-rounded)
__device__ float g_x32[(size_t)ROWS * DM];           // 16 MB  x pre-rounded
__device__ float g_WqkvT[(size_t)QKV_COLS * DM];     // 12 MB  [N][K] tf32
__device__ float g_WoutT[(size_t)DM * DM];           // 4 MB   [N][K] tf32
__device__ float g_rope_tab[(size_t)T_SEQ * 32 * 2]; // 512 KB (sin,cos)
// Packed per-head tf32 tensors [b][h][t][64]
__device__ float g_qpk[(size_t)ROWS * DM];           // 16 MB (pre-scaled 1/8)
__device__ float g_kpk[(size_t)ROWS * DM];           // 16 MB
__device__ float g_vpk[(size_t)ROWS * DM];           // 16 MB

__device__ __forceinline__ uint32_t f2tf32(float x) {
    uint32_t r;
    asm("cvt.rna.tf32.f32 %0, %1;" : "=r"(r) : "f"(x));
    return r;
}
__device__ __forceinline__ float f2tf32f(float x) {
    return __uint_as_float(f2tf32(x));
}
__device__ __forceinline__ uint32_t smem_u32(const void* p) {
    uint32_t a;
    asm("{ .reg .u64 t; cvta.to.shared.u64 t, %1; cvt.u32.u64 %0, t; }"
        : "=r"(a) : "l"(p));
    return a;
}
__device__ __forceinline__ void cp16(uint32_t dst, const void* src) {
    asm volatile("cp.async.cg.shared.global [%0], [%1], 16;"
                 :: "r"(dst), "l"(src));
}
#define CP_COMMIT() asm volatile("cp.async.commit_group;" ::: "memory")
#define CP_WAIT2()  asm volatile("cp.async.wait_group 2;" ::: "memory")
#define CP_WAIT1()  asm volatile("cp.async.wait_group 1;" ::: "memory")
#define CP_WAIT0()  asm volatile("cp.async.wait_group 0;" ::: "memory")

__device__ __forceinline__ void mma_tf32(
    float* c, uint32_t a0, uint32_t a1, uint32_t a2, uint32_t a3,
    uint32_t b0, uint32_t b1)
{
    asm volatile(
        "mma.sync.aligned.m16n8k8.row.col.f32.tf32.tf32.f32 "
        "{%0,%1,%2,%3}, {%4,%5,%6,%7}, {%8,%9}, {%0,%1,%2,%3};"
        : "+f"(c[0]), "+f"(c[1]), "+f"(c[2]), "+f"(c[3])
        : "r"(a0), "r"(a1), "r"(a2), "r"(a3), "r"(b0), "r"(b1));
}
__device__ __forceinline__ void ldsm_x4(
    uint32_t& r0, uint32_t& r1, uint32_t& r2, uint32_t& r3, uint32_t addr)
{
    asm volatile("ldmatrix.sync.aligned.m8n8.x4.shared.b16 {%0,%1,%2,%3}, [%4];"
                 : "=r"(r0), "=r"(r1), "=r"(r2), "=r"(r3) : "r"(addr));
}
__device__ __forceinline__ void ldsm_x2(
    uint32_t& r0, uint32_t& r1, uint32_t addr)
{
    asm volatile("ldmatrix.sync.aligned.m8n8.x2.shared.b16 {%0,%1}, [%2];"
                 : "=r"(r0), "=r"(r1) : "r"(addr));
}

// ===========================================================================
// Transpose + tf32 round: src [R][C] -> dst [C][R]
// ===========================================================================
__global__ void transpose_kernel(const float* __restrict__ src,
                                 float* __restrict__ dst, int R, int C)
{
    __shared__ float tile[32][33];
    int c0 = blockIdx.x * 32, r0 = blockIdx.y * 32;
    int x = threadIdx.x, y = threadIdx.y;   // 32 x 8
#pragma unroll
    for (int i = 0; i < 32; i += 8)
        tile[y + i][x] = f2tf32f(src[(size_t)(r0 + y + i) * C + c0 + x]);
    __syncthreads();
#pragma unroll
    for (int i = 0; i < 32; i += 8)
        dst[(size_t)(c0 + y + i) * R + r0 + x] = tile[x][y + i];
}

// x -> tf32-rounded copy
__global__ void convert_x_kernel(const float* __restrict__ x)
{
    int i = blockIdx.x * blockDim.x + threadIdx.x;
    float4 v = *(const float4*)(x + 4 * (size_t)i);
    float4 o = {f2tf32f(v.x), f2tf32f(v.y), f2tf32f(v.z), f2tf32f(v.w)};
    *(float4*)(g_x32 + 4 * (size_t)i) = o;
}

// ===========================================================================
// RoPE table
// ===========================================================================
__global__ void rope_table_kernel()
{
    int idx = blockIdx.x * blockDim.x + threadIdx.x;   // 65536
    if (idx >= T_SEQ * 32) return;
    int i = idx & 31;
    int t = idx >> 5;
    double ang = (double)t * pow(10000.0, -(double)i / 32.0);
    g_rope_tab[2 * idx + 0] = (float)sin(ang);
    g_rope_tab[2 * idx + 1] = (float)cos(ang);
}

// ===========================================================================
// Shared tf32 GEMM mainloop: 128x128 block, BK=16, 4-stage cp.async,
// ldmatrix fragment loads. Operands pre-rounded tf32. (R8-proven)
// ===========================================================================
#define SST 20
#define NSTG 4
#define STG_FLOATS (128 * SST)
#define GEMM_SMEM (NSTG * 2 * STG_FLOATS * 4)   // 81920 B

__device__ __forceinline__ void gemm_mainloop(
    const float* __restrict__ A, const float* __restrict__ Bt,
    int K, int bm, int bn, float acc[4][4][4], uint32_t* sm)
{
    const int tid  = threadIdx.x;
    const int lane = tid & 31;
    const int wid  = tid >> 5;
    const int wm   = (wid >> 2) * 64;
    const int wn   = (wid & 3) * 32;

    uint32_t* As = sm;
    uint32_t* Bs = sm + NSTG * STG_FLOATS;
    const uint32_t as0 = smem_u32(As);
    const uint32_t bs0 = smem_u32(Bs);
    const int r0 = tid >> 2, c4 = (tid & 3) * 4;

    const uint32_t a_lane = (uint32_t)((((lane >> 3) & 1) * 8 + (lane & 7)) * SST * 4
                                       + (lane >> 4) * 16);
    const uint32_t b_lane = (uint32_t)((lane & 7) * SST * 4
                                       + ((lane >> 3) & 1) * 16);

    auto issue = [&](int ch) {
        const int s  = ch & (NSTG - 1);
        const int k0 = ch << 4;
        const uint32_t ao = as0 + (uint32_t)(s * STG_FLOATS + r0 * SST + c4) * 4;
        const uint32_t bo = bs0 + (uint32_t)(s * STG_FLOATS + r0 * SST + c4) * 4;
        cp16(ao,                A  + (size_t)(bm + r0)      * K + k0 + c4);
        cp16(ao + 64 * SST * 4, A  + (size_t)(bm + r0 + 64) * K + k0 + c4);
        cp16(bo,                Bt + (size_t)(bn + r0)      * K + k0 + c4);
        cp16(bo + 64 * SST * 4, Bt + (size_t)(bn + r0 + 64) * K + k0 + c4);
        CP_COMMIT();
    };

    const int niter = K >> 4;
    issue(0); issue(1); issue(2);

    for (int it = 0; it < niter; it++) {
        CP_WAIT2();
        __syncthreads();
        if (it + 3 < niter) issue(it + 3);

        const uint32_t abase = as0 + (uint32_t)((it & (NSTG - 1)) * STG_FLOATS) * 4;
        const uint32_t bbase = bs0 + (uint32_t)((it & (NSTG - 1)) * STG_FLOATS) * 4;

#pragma unroll
        for (int ks = 0; ks < 16; ks += 8) {
            uint32_t afr[4][4], bfr[4][2];
#pragma unroll
            for (int mt = 0; mt < 4; mt++) {
                const uint32_t ad = abase
                    + (uint32_t)(((wm + mt * 16) * SST + ks) * 4) + a_lane;
                ldsm_x4(afr[mt][0], afr[mt][1], afr[mt][2], afr[mt][3], ad);
            }
#pragma unroll
            for (int nt = 0; nt < 4; nt++) {
                const uint32_t bd = bbase
                    + (uint32_t)(((wn + nt * 8) * SST + ks) * 4) + b_lane;
                ldsm_x2(bfr[nt][0], bfr[nt][1], bd);
            }
#pragma unroll
            for (int mt = 0; mt < 4; mt++)
#pragma unroll
                for (int nt = 0; nt < 4; nt++)
                    mma_tf32(acc[mt][nt], afr[mt][0], afr[mt][1], afr[mt][2],
                             afr[mt][3], bfr[nt][0], bfr[nt][1]);
        }
    }
}

// ---------------------------------------------------------------------------
// QKV GEMM with fused RoPE + per-head pack epilogue (R8-proven).
// ---------------------------------------------------------------------------
__global__ __launch_bounds__(256, 2) void gemm_qkv_fused(
    const float* __restrict__ A, const float* __restrict__ Bt, int K)
{
    extern __shared__ uint32_t sm[];
    const int tid  = threadIdx.x;
    const int lane = tid & 31;
    const int wid  = tid >> 5;
    const int wm   = (wid >> 2) * 64;
    const int wn   = (wid & 3) * 32;
    const int bm   = blockIdx.y * 128;
    const int bn   = blockIdx.x * 128;
    const int gid  = lane >> 2;
    const int tig  = lane & 3;

    float acc[4][4][4];
#pragma unroll
    for (int i = 0; i < 4; i++)
#pragma unroll
        for (int j = 0; j < 4; j++)
#pragma unroll
            for (int q = 0; q < 4; q++) acc[i][j][q] = 0.0f;

    gemm_mainloop(A, Bt, K, bm, bn, acc, sm);

#pragma unroll
    for (int mt = 0; mt < 4; mt++) {
        const int rb = bm + wm + mt * 16 + gid;
#pragma unroll
        for (int nt = 0; nt < 4; nt++) {
            const int c  = bn + wn + nt * 8 + 2 * tig;
            const int region = c >> 10;
            const int cc = c & 1023;
            const int h  = cc >> 6;
            const int d  = cc & 63;
            const int i2 = d >> 1;
#pragma unroll
            for (int half = 0; half < 2; half++) {
                const int r = rb + half * 8;
                const int t = r & (T_SEQ - 1);
                const int b = r >> 11;
                const float a0 = acc[mt][nt][2 * half + 0];
                const float a1 = acc[mt][nt][2 * half + 1];
                const size_t dst =
                    ((size_t)(b * NHEAD + h) * T_SEQ + t) * HDIM + d;
                if (region == 2) {
                    float2 o = {f2tf32f(a0), f2tf32f(a1)};
                    *(float2*)&g_vpk[dst] = o;
                } else {
                    const float sn = g_rope_tab[2 * (t * 32 + i2) + 0];
                    const float cs = g_rope_tab[2 * (t * 32 + i2) + 1];
                    float o0 = a0 * cs - a1 * sn;
                    float o1 = a1 * cs + a0 * sn;
                    if (region == 0) {
                        float2 o = {f2tf32f(o0 * 0.125f), f2tf32f(o1 * 0.125f)};
                        *(float2*)&g_qpk[dst] = o;
                    } else {
                        float2 o = {f2tf32f(o0), f2tf32f(o1)};
                        *(float2*)&g_kpk[dst] = o;
                    }
                }
            }
        }
    }
}

// ---------------------------------------------------------------------------
// Plain tf32 GEMM (output projection)
// ---------------------------------------------------------------------------
__global__ __launch_bounds__(256, 2) void gemm_tf32(
    const float* __restrict__ A, const float* __restrict__ Bt,
    float* __restrict__ C, int N, int K)
{
    extern __shared__ uint32_t sm[];
    const int tid  = threadIdx.x;
    const int lane = tid & 31;
    const int wid  = tid >> 5;
    const int wm   = (wid >> 2) * 64;
    const int wn   = (wid & 3) * 32;
    const int bm   = blockIdx.y * 128;
    const int bn   = blockIdx.x * 128;
    const int gid  = lane >> 2;
    const int tig  = lane & 3;

    float acc[4][4][4];
#pragma unroll
    for (int i = 0; i < 4; i++)
#pragma unroll
        for (int j = 0; j < 4; j++)
#pragma unroll
            for (int q = 0; q < 4; q++) acc[i][j][q] = 0.0f;

    gemm_mainloop(A, Bt, K, bm, bn, acc, sm);

#pragma unroll
    for (int mt = 0; mt < 4; mt++) {
        const int rb = bm + wm + mt * 16;
#pragma unroll
        for (int nt = 0; nt < 4; nt++) {
            const int cb = bn + wn + nt * 8 + 2 * tig;
            float2 lo = {acc[mt][nt][0], acc[mt][nt][1]};
            float2 hi = {acc[mt][nt][2], acc[mt][nt][3]};
            *(float2*)(C + (size_t)(rb + gid)     * N + cb) = lo;
            *(float2*)(C + (size_t)(rb + gid + 8) * N + cb) = hi;
        }
    }
}

// ===========================================================================
// Tensor-core causal flash attention — 64 q-rows per CTA, 128 threads
// (4 warps). 2 CTAs/SM with INDEPENDENT barriers: one CTA's softmax overlaps
// the other's MMAs. Per-warp code identical to R8 (strides 68 / 72).
// ===========================================================================
#define SKP 68
#define SV  72
#define QROWS 64
#define FA_THREADS 128
#define FA_SMEM ((2 * 64 * SKP + 2 * 64 * SV + QROWS * SKP) * 4)   // 89088 B

__global__ __launch_bounds__(FA_THREADS) void flash_attn_tc()
{
    extern __shared__ uint32_t smu[];
    uint32_t* Ksm = smu;                       // [2][key][d]  stride 68
    uint32_t* Vsm = Ksm + 2 * 64 * SKP;        // [2][key][d]  stride 72
    uint32_t* Psm = Vsm + 2 * 64 * SV;         // [m][key]     stride 68

    const int tid  = threadIdx.x;
    const int lane = tid & 31;
    const int wid  = tid >> 5;                 // 0..3
    const int gid  = lane >> 2;
    const int tig  = lane & 3;
    const int qi = (int)(gridDim.x - 1 - blockIdx.x);   // descending length
    const int h = blockIdx.y, b = blockIdx.z;
    const int qbase = qi * QROWS;
    const int bh = b * NHEAD + h;
    const int wrow = 16 * wid;

    const uint32_t ksm0 = smem_u32(Ksm);
    const uint32_t vsm0 = smem_u32(Vsm);
    const uint32_t psm0 = smem_u32(Psm);
    const float* kbase_p = g_kpk + (size_t)bh * T_SEQ * HDIM;
    const float* vbase_p = g_vpk + (size_t)bh * T_SEQ * HDIM;

    const uint32_t k_lane = (uint32_t)((lane & 7) * SKP * 4 + (lane >> 3) * 16);
    const uint32_t p_lane = (uint32_t)((((lane >> 3) & 1) * 8 + (lane & 7)) * SKP * 4
                                       + (lane >> 4) * 16);

    // 128 threads: each loads 32 floats of K and of V per tile (8 cp16 each)
    auto issue_kv = [&](int kt, int st) {
        const int n = tid >> 1;                 // key 0..63
        const int c = (tid & 1) * 32;           // float offset
        const size_t go = (size_t)(kt * 64 + n) * HDIM + c;
        const uint32_t ko = (uint32_t)(st * 64 * SKP + n * SKP + c) * 4;
        const uint32_t vo = (uint32_t)(st * 64 * SV  + n * SV  + c) * 4;
#pragma unroll
        for (int j = 0; j < 8; j++) {
            cp16(ksm0 + ko + j * 16, kbase_p + go + j * 4);
            cp16(vsm0 + vo + j * 16, vbase_p + go + j * 4);
        }
    };

    // stage Q (tf32, pre-scaled) into Psm: 128 threads cover 64 rows
    {
        int m = tid >> 1;
        int d0 = (tid & 1) * 32;
        const float* src = g_qpk + ((size_t)bh * T_SEQ + qbase + m) * HDIM + d0;
#pragma unroll
        for (int j = 0; j < 8; j++) {
            uint4 v = *(const uint4*)(src + 4 * j);
            *(uint4*)&Psm[m * SKP + d0 + 4 * j] = v;
        }
    }

    const int nkt = qbase / 64 + 1;
    issue_kv(0, 0);
    CP_COMMIT();
    __syncthreads();

    // hoist Q fragments via ldmatrix
    uint32_t qf[8][4];
#pragma unroll
    for (int ks = 0; ks < 8; ks++) {
        const uint32_t qa = psm0 + (uint32_t)((wrow * SKP + ks * 8) * 4) + p_lane;
        ldsm_x4(qf[ks][0], qf[ks][1], qf[ks][2], qf[ks][3], qa);
    }

    float Oacc[8][4];
#pragma unroll
    for (int nt = 0; nt < 8; nt++)
#pragma unroll
        for (int q = 0; q < 4; q++) Oacc[nt][q] = 0.0f;
    float mrow0 = -1e30f, mrow1 = -1e30f, lrow0 = 0.0f, lrow1 = 0.0f;

    for (int kt = 0; kt < nkt; kt++) {
        const int st = kt & 1;
        const int kb = kt * 64;
        const bool more = (kt + 1) < nkt;
        if (more) { issue_kv(kt + 1, st ^ 1); CP_COMMIT(); }
        if (more) { CP_WAIT1(); } else { CP_WAIT0(); }
        __syncthreads();

        const uint32_t kst = ksm0 + (uint32_t)(st * 64 * SKP * 4);
        const uint32_t* Vst = Vsm + st * 64 * SV;

        // ---- S = Q @ K^T ----
        float sacc[8][4];
#pragma unroll
        for (int nt = 0; nt < 8; nt++)
#pragma unroll
            for (int q = 0; q < 4; q++) sacc[nt][q] = 0.0f;

#pragma unroll
        for (int kp = 0; kp < 4; kp++) {
#pragma unroll
            for (int nt = 0; nt < 8; nt++) {
                uint32_t b0, b1, b2, b3;
                const uint32_t ka = kst
                    + (uint32_t)((nt * 8 * SKP + kp * 16) * 4) + k_lane;
                ldsm_x4(b0, b1, b2, b3, ka);
                mma_tf32(sacc[nt], qf[2 * kp][0], qf[2 * kp][1],
                         qf[2 * kp][2], qf[2 * kp][3], b0, b1);
                mma_tf32(sacc[nt], qf[2 * kp + 1][0], qf[2 * kp + 1][1],
                         qf[2 * kp + 1][2], qf[2 * kp + 1][3], b2, b3);
            }
        }

        // ---- causal mask (last tile only) ----
        const int r0g = qbase + wrow + gid;
        if (kb + 63 > qbase) {
#pragma unroll
            for (int nt = 0; nt < 8; nt++) {
                int col = kb + nt * 8 + 2 * tig;
                if (col     > r0g)     sacc[nt][0] = -1e30f;
                if (col + 1 > r0g)     sacc[nt][1] = -1e30f;
                if (col     > r0g + 8) sacc[nt][2] = -1e30f;
                if (col + 1 > r0g + 8) sacc[nt][3] = -1e30f;
            }
        }

        // ---- online softmax ----
        float mx0 = -1e30f, mx1 = -1e30f;
#pragma unroll
        for (int nt = 0; nt < 8; nt++) {
            mx0 = fmaxf(mx0, fmaxf(sacc[nt][0], sacc[nt][1]));
            mx1 = fmaxf(mx1, fmaxf(sacc[nt][2], sacc[nt][3]));
        }
        mx0 = fmaxf(mx0, __shfl_xor_sync(0xffffffffu, mx0, 1));
        mx0 = fmaxf(mx0, __shfl_xor_sync(0xffffffffu, mx0, 2));
        mx1 = fmaxf(mx1, __shfl_xor_sync(0xffffffffu, mx1, 1));
        mx1 = fmaxf(mx1, __shfl_xor_sync(0xffffffffu, mx1, 2));
        const float nm0 = fmaxf(mrow0, mx0);
        const float nm1 = fmaxf(mrow1, mx1);

        float sum0 = 0.0f, sum1 = 0.0f;
#pragma unroll
        for (int nt = 0; nt < 8; nt++) {
            float p00 = __expf(sacc[nt][0] - nm0);
            float p01 = __expf(sacc[nt][1] - nm0);
            float p10 = __expf(sacc[nt][2] - nm1);
            float p11 = __expf(sacc[nt][3] - nm1);
            sum0 += p00 + p01;
            sum1 += p10 + p11;
            uint2 u0 = {f2tf32(p00), f2tf32(p01)};
            uint2 u1 = {f2tf32(p10), f2tf32(p11)};
            *(uint2*)&Psm[(wrow + gid)     * SKP + nt * 8 + 2 * tig] = u0;
            *(uint2*)&Psm[(wrow + gid + 8) * SKP + nt * 8 + 2 * tig] = u1;
        }
        sum0 += __shfl_xor_sync(0xffffffffu, sum0, 1);
        sum0 += __shfl_xor_sync(0xffffffffu, sum0, 2);
        sum1 += __shfl_xor_sync(0xffffffffu, sum1, 1);
        sum1 += __shfl_xor_sync(0xffffffffu, sum1, 2);

        const float a0 = __expf(mrow0 - nm0);
        const float a1 = __expf(mrow1 - nm1);
        lrow0 = lrow0 * a0 + sum0;
        lrow1 = lrow1 * a1 + sum1;
        mrow0 = nm0; mrow1 = nm1;
#pragma unroll
        for (int nt = 0; nt < 8; nt++) {
            Oacc[nt][0] *= a0; Oacc[nt][1] *= a0;
            Oacc[nt][2] *= a1; Oacc[nt][3] *= a1;
        }
        __syncwarp();

        // ---- O += P @ V ----
#pragma unroll
        for (int ks = 0; ks < 8; ks++) {
            uint32_t a0f, a1f, a2f, a3f;
            const uint32_t pa = psm0
                + (uint32_t)((wrow * SKP + ks * 8) * 4) + p_lane;
            ldsm_x4(a0f, a1f, a2f, a3f, pa);
#pragma unroll
            for (int nt = 0; nt < 8; nt++) {
                uint32_t b0 = Vst[(ks * 8 + tig)     * SV + nt * 8 + gid];
                uint32_t b1 = Vst[(ks * 8 + tig + 4) * SV + nt * 8 + gid];
                mma_tf32(Oacc[nt], a0f, a1f, a2f, a3f, b0, b1);
            }
        }
        __syncthreads();
    }

    const float i0 = 1.0f / lrow0;
    const float i1 = 1.0f / lrow1;
    const int r0g = qbase + wrow + gid;
#pragma unroll
    for (int nt = 0; nt < 8; nt++) {
        const int c = h * HDIM + nt * 8 + 2 * tig;
        float2 lo = {f2tf32f(Oacc[nt][0] * i0), f2tf32f(Oacc[nt][1] * i0)};
        float2 hi = {f2tf32f(Oacc[nt][2] * i1), f2tf32f(Oacc[nt][3] * i1)};
        *(float2*)&g_attn[((size_t)b * T_SEQ + r0g)     * DM + c] = lo;
        *(float2*)&g_attn[((size_t)b * T_SEQ + r0g + 8) * DM + c] = hi;
    }
}

// ===========================================================================
extern "C" void kernel_launch(void* const* d_in, const int* in_sizes, int n_in,
                              void* d_out, int out_size)
{
    const float* x    = (const float*)d_in[0];
    const float* Wqkv = (const float*)d_in[1];
    const float* Wout = (const float*)d_in[2];
    float* out = (float*)d_out;

    float *attn = nullptr, *wqkvT = nullptr, *woutT = nullptr, *x32 = nullptr;
    cudaGetSymbolAddress((void**)&attn,  g_attn);
    cudaGetSymbolAddress((void**)&wqkvT, g_WqkvT);
    cudaGetSymbolAddress((void**)&woutT, g_WoutT);
    cudaGetSymbolAddress((void**)&x32,   g_x32);

    cudaFuncSetAttribute(gemm_qkv_fused,
                         cudaFuncAttributeMaxDynamicSharedMemorySize, GEMM_SMEM);
    cudaFuncSetAttribute(gemm_tf32,
                         cudaFuncAttributeMaxDynamicSharedMemorySize, GEMM_SMEM);
    cudaFuncSetAttribute(flash_attn_tc,
                         cudaFuncAttributeMaxDynamicSharedMemorySize, FA_SMEM);

    // 0) RoPE table, weight transposes (+tf32 round), x round
    rope_table_kernel<<<(T_SEQ * 32 + 255) / 256, 256>>>();
    transpose_kernel<<<dim3(QKV_COLS / 32, DM / 32), dim3(32, 8)>>>(
        Wqkv, wqkvT, DM, QKV_COLS);
    transpose_kernel<<<dim3(DM / 32, DM / 32), dim3(32, 8)>>>(
        Wout, woutT, DM, DM);
    convert_x_kernel<<<(ROWS * DM / 4) / 256, 256>>>(x);

    // 1) QKV projection + fused RoPE + per-head pack
    gemm_qkv_fused<<<dim3(QKV_COLS / 128, ROWS / 128), 256, GEMM_SMEM>>>(
        x32, wqkvT, DM);

    // 2) Causal flash attention (64-row CTAs, 2 CTAs/SM, independent barriers)
    flash_attn_tc<<<dim3(T_SEQ / QROWS, NHEAD, B_BATCH), FA_THREADS, FA_SMEM>>>();

    // 3) Output projection
    gemm_tf32<<<dim3(DM / 128, ROWS / 128), 256, GEMM_SMEM>>>(
        attn, woutT, out, DM, DM);
}

// round 14
// speedup vs baseline: 1.9461x; 1.9461x over previous
#include <cuda_runtime.h>
#include <cuda_fp16.h>
#include <cstdint>
#include <math.h>

#define T_SEQ    2048
#define B_BATCH  2
#define DM       1024
#define NHEAD    16
#define HDIM     64
#define ROWS     (B_BATCH * T_SEQ)      // 4096
#define QKV_COLS (3 * DM)               // 3072

// Scratch (allocation-guard compliant: device globals) — all fp16
__device__ __half g_attn16[(size_t)ROWS * DM];          // 8 MB
__device__ __half g_x16[(size_t)ROWS * DM];             // 8 MB
__device__ __half g_WqkvT16[(size_t)QKV_COLS * DM];     // 6 MB [N][K]
__device__ __half g_WoutT16[(size_t)DM * DM];           // 2 MB [N][K]
__device__ float  g_rope_tab[(size_t)T_SEQ * 32 * 2];   // 512 KB (sin,cos)
// Packed per-head fp16 tensors [b][h][t][64]
__device__ __half g_qpk[(size_t)ROWS * DM];             // 8 MB (q * 1/8)
__device__ __half g_kpk[(size_t)ROWS * DM];             // 8 MB
__device__ __half g_vpk[(size_t)ROWS * DM];             // 8 MB

__device__ __forceinline__ uint32_t smem_u32(const void* p) {
    uint32_t a;
    asm("{ .reg .u64 t; cvta.to.shared.u64 t, %1; cvt.u32.u64 %0, t; }"
        : "=r"(a) : "l"(p));
    return a;
}
__device__ __forceinline__ void cp16(uint32_t dst, const void* src) {
    asm volatile("cp.async.cg.shared.global [%0], [%1], 16;"
                 :: "r"(dst), "l"(src));
}
#define CP_COMMIT() asm volatile("cp.async.commit_group;" ::: "memory")
#define CP_WAIT2()  asm volatile("cp.async.wait_group 2;" ::: "memory")
#define CP_WAIT1()  asm volatile("cp.async.wait_group 1;" ::: "memory")
#define CP_WAIT0()  asm volatile("cp.async.wait_group 0;" ::: "memory")

__device__ __forceinline__ void mma_f16(
    float* c, uint32_t a0, uint32_t a1, uint32_t a2, uint32_t a3,
    uint32_t b0, uint32_t b1)
{
    asm volatile(
        "mma.sync.aligned.m16n8k16.row.col.f32.f16.f16.f32 "
        "{%0,%1,%2,%3}, {%4,%5,%6,%7}, {%8,%9}, {%0,%1,%2,%3};"
        : "+f"(c[0]), "+f"(c[1]), "+f"(c[2]), "+f"(c[3])
        : "r"(a0), "r"(a1), "r"(a2), "r"(a3), "r"(b0), "r"(b1));
}
__device__ __forceinline__ void ldsm_x4(
    uint32_t& r0, uint32_t& r1, uint32_t& r2, uint32_t& r3, uint32_t addr)
{
    asm volatile("ldmatrix.sync.aligned.m8n8.x4.shared.b16 {%0,%1,%2,%3}, [%4];"
                 : "=r"(r0), "=r"(r1), "=r"(r2), "=r"(r3) : "r"(addr));
}
__device__ __forceinline__ void ldsm_x2(
    uint32_t& r0, uint32_t& r1, uint32_t addr)
{
    asm volatile("ldmatrix.sync.aligned.m8n8.x2.shared.b16 {%0,%1}, [%2];"
                 : "=r"(r0), "=r"(r1) : "r"(addr));
}
__device__ __forceinline__ void ldsm_x2_trans(
    uint32_t& r0, uint32_t& r1, uint32_t addr)
{
    asm volatile("ldmatrix.sync.aligned.m8n8.x2.trans.shared.b16 {%0,%1}, [%2];"
                 : "=r"(r0), "=r"(r1) : "r"(addr));
}

// ===========================================================================
// Transpose + fp16 round: src [R][C] fp32 -> dst [C][R] fp16
// ===========================================================================
__global__ void transpose_f16_kernel(const float* __restrict__ src,
                                     __half* __restrict__ dst, int R, int C)
{
    __shared__ float tile[32][33];
    int c0 = blockIdx.x * 32, r0 = blockIdx.y * 32;
    int x = threadIdx.x, y = threadIdx.y;   // 32 x 8
#pragma unroll
    for (int i = 0; i < 32; i += 8)
        tile[y + i][x] = src[(size_t)(r0 + y + i) * C + c0 + x];
    __syncthreads();
#pragma unroll
    for (int i = 0; i < 32; i += 8)
        dst[(size_t)(c0 + y + i) * R + r0 + x] = __float2half_rn(tile[x][y + i]);
}

// x -> fp16 copy
__global__ void convert_x_kernel(const float* __restrict__ x)
{
    int i = blockIdx.x * blockDim.x + threadIdx.x;
    float4 v = *(const float4*)(x + 4 * (size_t)i);
    __half2 h0 = __floats2half2_rn(v.x, v.y);
    __half2 h1 = __floats2half2_rn(v.z, v.w);
    *(__half2*)&g_x16[4 * (size_t)i]     = h0;
    *(__half2*)&g_x16[4 * (size_t)i + 2] = h1;
}

// ===========================================================================
// RoPE table
// ===========================================================================
__global__ void rope_table_kernel()
{
    int idx = blockIdx.x * blockDim.x + threadIdx.x;   // 65536
    if (idx >= T_SEQ * 32) return;
    int i = idx & 31;
    int t = idx >> 5;
    double ang = (double)t * pow(10000.0, -(double)i / 32.0);
    g_rope_tab[2 * idx + 0] = (float)sin(ang);
    g_rope_tab[2 * idx + 1] = (float)cos(ang);
}

// ===========================================================================
// fp16 GEMM mainloop: 128x128 tile, BK=32 halves (64B rows), 4-stage cp.async,
// ldmatrix frags, m16n8k16 fp16 mma w/ fp32 accum. Row stride 40 halves (80B)
// -> banks 20r mod 32 distinct: conflict-free ldmatrix phases.
// ===========================================================================
#define SSTH 40
#define NSTG 4
#define STG_HALVES (128 * SSTH)
#define GEMM_SMEM (NSTG * 2 * STG_HALVES * 2)   // 81920 B

__device__ __forceinline__ void gemm_mainloop_f16(
    const __half* __restrict__ A, const __half* __restrict__ Bt,
    int K, int bm, int bn, float acc[4][4][4], __half* sm)
{
    const int tid  = threadIdx.x;
    const int lane = tid & 31;
    const int wid  = tid >> 5;
    const int wm   = (wid >> 2) * 64;
    const int wn   = (wid & 3) * 32;

    __half* As = sm;
    __half* Bs = sm + NSTG * STG_HALVES;
    const uint32_t as0 = smem_u32(As);
    const uint32_t bs0 = smem_u32(Bs);
    const int r0 = tid >> 1;               // row 0..127
    const int c0 = (tid & 1) * 16;         // half offset (16 halves = 32B)

    const uint32_t a_lane = (uint32_t)((((lane >> 3) & 1) * 8 + (lane & 7)) * (SSTH * 2)
                                       + (lane >> 4) * 16);
    const uint32_t b_lane = (uint32_t)((lane & 7) * (SSTH * 2)
                                       + ((lane >> 3) & 1) * 16);

    auto issue = [&](int ch) {
        const int s  = ch & (NSTG - 1);
        const int k0 = ch << 5;            // halves
        const uint32_t ao = as0 + (uint32_t)(s * STG_HALVES + r0 * SSTH + c0) * 2;
        const uint32_t bo = bs0 + (uint32_t)(s * STG_HALVES + r0 * SSTH + c0) * 2;
        cp16(ao,      A  + (size_t)(bm + r0) * K + k0 + c0);
        cp16(ao + 16, A  + (size_t)(bm + r0) * K + k0 + c0 + 8);
        cp16(bo,      Bt + (size_t)(bn + r0) * K + k0 + c0);
        cp16(bo + 16, Bt + (size_t)(bn + r0) * K + k0 + c0 + 8);
        CP_COMMIT();
    };

    const int niter = K >> 5;              // BK = 32 halves
    issue(0); issue(1); issue(2);

    for (int it = 0; it < niter; it++) {
        CP_WAIT2();
        __syncthreads();
        if (it + 3 < niter) issue(it + 3);

        const uint32_t abase = as0 + (uint32_t)((it & (NSTG - 1)) * STG_HALVES) * 2;
        const uint32_t bbase = bs0 + (uint32_t)((it & (NSTG - 1)) * STG_HALVES) * 2;

#pragma unroll
        for (int ks = 0; ks < 2; ks++) {   // two k16 steps, +32B each
            uint32_t afr[4][4], bfr[4][2];
#pragma unroll
            for (int mt = 0; mt < 4; mt++) {
                const uint32_t ad = abase
                    + (uint32_t)((wm + mt * 16) * (SSTH * 2)) + ks * 32 + a_lane;
                ldsm_x4(afr[mt][0], afr[mt][1], afr[mt][2], afr[mt][3], ad);
            }
#pragma unroll
            for (int nt = 0; nt < 4; nt++) {
                const uint32_t bd = bbase
                    + (uint32_t)((wn + nt * 8) * (SSTH * 2)) + ks * 32 + b_lane;
                ldsm_x2(bfr[nt][0], bfr[nt][1], bd);
            }
#pragma unroll
            for (int mt = 0; mt < 4; mt++)
#pragma unroll
                for (int nt = 0; nt < 4; nt++)
                    mma_f16(acc[mt][nt], afr[mt][0], afr[mt][1], afr[mt][2],
                            afr[mt][3], bfr[nt][0], bfr[nt][1]);
        }
    }
}

// ---------------------------------------------------------------------------
// QKV GEMM (fp16) with fused RoPE + per-head pack epilogue (fp16 outputs).
// ---------------------------------------------------------------------------
__global__ __launch_bounds__(256, 2) void gemm_qkv_fused(
    const __half* __restrict__ A, const __half* __restrict__ Bt, int K)
{
    extern __shared__ __half smh[];
    const int tid  = threadIdx.x;
    const int lane = tid & 31;
    const int wid  = tid >> 5;
    const int wm   = (wid >> 2) * 64;
    const int wn   = (wid & 3) * 32;
    const int bm   = blockIdx.y * 128;
    const int bn   = blockIdx.x * 128;
    const int gid  = lane >> 2;
    const int tig  = lane & 3;

    float acc[4][4][4];
#pragma unroll
    for (int i = 0; i < 4; i++)
#pragma unroll
        for (int j = 0; j < 4; j++)
#pragma unroll
            for (int q = 0; q < 4; q++) acc[i][j][q] = 0.0f;

    gemm_mainloop_f16(A, Bt, K, bm, bn, acc, smh);

#pragma unroll
    for (int mt = 0; mt < 4; mt++) {
        const int rb = bm + wm + mt * 16 + gid;
#pragma unroll
        for (int nt = 0; nt < 4; nt++) {
            const int c  = bn + wn + nt * 8 + 2 * tig;
            const int region = c >> 10;
            const int cc = c & 1023;
            const int h  = cc >> 6;
            const int d  = cc & 63;
            const int i2 = d >> 1;
#pragma unroll
            for (int half = 0; half < 2; half++) {
                const int r = rb + half * 8;
                const int t = r & (T_SEQ - 1);
                const int b = r >> 11;
                const float a0 = acc[mt][nt][2 * half + 0];
                const float a1 = acc[mt][nt][2 * half + 1];
                const size_t dst =
                    ((size_t)(b * NHEAD + h) * T_SEQ + t) * HDIM + d;
                if (region == 2) {
                    *(__half2*)&g_vpk[dst] = __floats2half2_rn(a0, a1);
                } else {
                    const float sn = g_rope_tab[2 * (t * 32 + i2) + 0];
                    const float cs = g_rope_tab[2 * (t * 32 + i2) + 1];
                    float o0 = a0 * cs - a1 * sn;
                    float o1 = a1 * cs + a0 * sn;
                    if (region == 0) {
                        *(__half2*)&g_qpk[dst] =
                            __floats2half2_rn(o0 * 0.125f, o1 * 0.125f);
                    } else {
                        *(__half2*)&g_kpk[dst] = __floats2half2_rn(o0, o1);
                    }
                }
            }
        }
    }
}

// ---------------------------------------------------------------------------
// Plain fp16 GEMM, fp32 output (output projection)
// ---------------------------------------------------------------------------
__global__ __launch_bounds__(256, 2) void gemm_f16(
    const __half* __restrict__ A, const __half* __restrict__ Bt,
    float* __restrict__ C, int N, int K)
{
    extern __shared__ __half smh[];
    const int tid  = threadIdx.x;
    const int lane = tid & 31;
    const int wid  = tid >> 5;
    const int wm   = (wid >> 2) * 64;
    const int wn   = (wid & 3) * 32;
    const int bm   = blockIdx.y * 128;
    const int bn   = blockIdx.x * 128;
    const int gid  = lane >> 2;
    const int tig  = lane & 3;

    float acc[4][4][4];
#pragma unroll
    for (int i = 0; i < 4; i++)
#pragma unroll
        for (int j = 0; j < 4; j++)
#pragma unroll
            for (int q = 0; q < 4; q++) acc[i][j][q] = 0.0f;

    gemm_mainloop_f16(A, Bt, K, bm, bn, acc, smh);

#pragma unroll
    for (int mt = 0; mt < 4; mt++) {
        const int rb = bm + wm + mt * 16;
#pragma unroll
        for (int nt = 0; nt < 4; nt++) {
            const int cb = bn + wn + nt * 8 + 2 * tig;
            float2 lo = {acc[mt][nt][0], acc[mt][nt][1]};
            float2 hi = {acc[mt][nt][2], acc[mt][nt][3]};
            *(float2*)(C + (size_t)(rb + gid)     * N + cb) = lo;
            *(float2*)(C + (size_t)(rb + gid + 8) * N + cb) = hi;
        }
    }
}

// ===========================================================================
// fp16 tensor-core causal flash attention (R8 structure: 128 q-rows, 8 warps).
// Strides 72 halves (144B): ldmatrix phases bank-perfect (4r mod 32).
// V via ldmatrix.x2.trans. smem 54KB -> natural 2 CTAs/SM.
// ===========================================================================
#define SKP 72
#define SV  72
#define FA_SMEM ((2 * 64 * SKP + 2 * 64 * SV + 128 * SKP) * 2)   // 55296 B

__global__ __launch_bounds__(256) void flash_attn_tc()
{
    extern __shared__ __half smh[];
    __half* Ksm = smh;                       // [2][key][d]  stride 72
    __half* Vsm = Ksm + 2 * 64 * SKP;        // [2][key][d]  stride 72
    __half* Psm = Vsm + 2 * 64 * SV;         // [m][key]     stride 72

    const int tid  = threadIdx.x;
    const int lane = tid & 31;
    const int wid  = tid >> 5;
    const int gid  = lane >> 2;
    const int tig  = lane & 3;
    const int qi = (int)(gridDim.x - 1 - blockIdx.x);
    const int h = blockIdx.y, b = blockIdx.z;
    const int qbase = qi * 128;
    const int bh = b * NHEAD + h;
    const int wrow = 16 * wid;

    const uint32_t ksm0 = smem_u32(Ksm);
    const uint32_t vsm0 = smem_u32(Vsm);
    const uint32_t psm0 = smem_u32(Psm);
    const __half* kbase_p = g_kpk + (size_t)bh * T_SEQ * HDIM;
    const __half* vbase_p = g_vpk + (size_t)bh * T_SEQ * HDIM;

    // ldmatrix lane byte offsets
    const uint32_t k_lane = (uint32_t)((lane & 7) * (SKP * 2)
                                       + ((lane >> 3) & 1) * 16);
    const uint32_t p_lane = (uint32_t)((((lane >> 3) & 1) * 8 + (lane & 7)) * (SKP * 2)
                                       + (lane >> 4) * 16);
    const uint32_t v_lane = (uint32_t)((lane & 15) * (SV * 2));

    // 256 threads: each loads 32B of K and of V per tile (2 cp16 each)
    auto issue_kv = [&](int kt, int st) {
        const int n = tid >> 2;                 // key 0..63
        const int q = (tid & 3) * 16;           // half offset (32B chunks)
        const size_t go = (size_t)(kt * 64 + n) * HDIM + q;
        const uint32_t ko = (uint32_t)(st * 64 * SKP + n * SKP + q) * 2;
        const uint32_t vo = (uint32_t)(st * 64 * SV  + n * SV  + q) * 2;
        cp16(ko + ksm0,      kbase_p + go);
        cp16(ko + ksm0 + 16, kbase_p + go + 8);
        cp16(vo + vsm0,      vbase_p + go);
        cp16(vo + vsm0 + 16, vbase_p + go + 8);
    };

    // stage Q (fp16, pre-scaled) into Psm: 256 threads cover 128 rows
    {
        int m = tid >> 1;
        int d0 = (tid & 1) * 32;
        const __half* src = g_qpk + ((size_t)bh * T_SEQ + qbase + m) * HDIM + d0;
#pragma unroll
        for (int j = 0; j < 4; j++) {
            uint4 v = *(const uint4*)(src + 8 * j);
            *(uint4*)&Psm[m * SKP + d0 + 8 * j] = v;
        }
    }

    const int nkt = qbase / 64 + 2;
    issue_kv(0, 0);
    CP_COMMIT();
    __syncthreads();

    // hoist Q fragments (4 k16-steps over d=64)
    uint32_t qf[4][4];
#pragma unroll
    for (int kp = 0; kp < 4; kp++) {
        const uint32_t qa = psm0 + (uint32_t)(wrow * (SKP * 2)) + kp * 32 + p_lane;
        ldsm_x4(qf[kp][0], qf[kp][1], qf[kp][2], qf[kp][3], qa);
    }

    float Oacc[8][4];
#pragma unroll
    for (int nt = 0; nt < 8; nt++)
#pragma unroll
        for (int q = 0; q < 4; q++) Oacc[nt][q] = 0.0f;
    float mrow0 = -1e30f, mrow1 = -1e30f, lrow0 = 0.0f, lrow1 = 0.0f;

    for (int kt = 0; kt < nkt; kt++) {
        const int st = kt & 1;
        const int kb = kt * 64;
        const bool more = (kt + 1) < nkt;
        if (more) { issue_kv(kt + 1, st ^ 1); CP_COMMIT(); }
        if (more) { CP_WAIT1(); } else { CP_WAIT0(); }
        __syncthreads();

        const uint32_t kst = ksm0 + (uint32_t)(st * 64 * SKP * 2);
        const uint32_t vst = vsm0 + (uint32_t)(st * 64 * SV * 2);

        // ---- S = Q @ K^T  (4 k16-steps over d) ----
        float sacc[8][4];
#pragma unroll
        for (int nt = 0; nt < 8; nt++)
#pragma unroll
            for (int q = 0; q < 4; q++) sacc[nt][q] = 0.0f;

#pragma unroll
        for (int kp = 0; kp < 4; kp++) {
#pragma unroll
            for (int nt = 0; nt < 8; nt++) {
                uint32_t b0, b1;
                const uint32_t ka = kst
                    + (uint32_t)(nt * 8 * (SKP * 2)) + kp * 32 + k_lane;
                ldsm_x2(b0, b1, ka);
                mma_f16(sacc[nt], qf[kp][0], qf[kp][1], qf[kp][2], qf[kp][3],
                        b0, b1);
            }
        }

        // ---- causal mask (last two tiles only) ----
        const int r0g = qbase + wrow + gid;
        if (kb + 63 > qbase) {
#pragma unroll
            for (int nt = 0; nt < 8; nt++) {
                int col = kb + nt * 8 + 2 * tig;
                if (col     > r0g)     sacc[nt][0] = -1e30f;
                if (col + 1 > r0g)     sacc[nt][1] = -1e30f;
                if (col     > r0g + 8) sacc[nt][2] = -1e30f;
                if (col + 1 > r0g + 8) sacc[nt][3] = -1e30f;
            }
        }

        // ---- online softmax ----
        float mx0 = -1e30f, mx1 = -1e30f;
#pragma unroll
        for (int nt = 0; nt < 8; nt++) {
            mx0 = fmaxf(mx0, fmaxf(sacc[nt][0], sacc[nt][1]));
            mx1 = fmaxf(mx1, fmaxf(sacc[nt][2], sacc[nt][3]));
        }
        mx0 = fmaxf(mx0, __shfl_xor_sync(0xffffffffu, mx0, 1));
        mx0 = fmaxf(mx0, __shfl_xor_sync(0xffffffffu, mx0, 2));
        mx1 = fmaxf(mx1, __shfl_xor_sync(0xffffffffu, mx1, 1));
        mx1 = fmaxf(mx1, __shfl_xor_sync(0xffffffffu, mx1, 2));
        const float nm0 = fmaxf(mrow0, mx0);
        const float nm1 = fmaxf(mrow1, mx1);

        float sum0 = 0.0f, sum1 = 0.0f;
#pragma unroll
        for (int nt = 0; nt < 8; nt++) {
            float p00 = __expf(sacc[nt][0] - nm0);
            float p01 = __expf(sacc[nt][1] - nm0);
            float p10 = __expf(sacc[nt][2] - nm1);
            float p11 = __expf(sacc[nt][3] - nm1);
            sum0 += p00 + p01;
            sum1 += p10 + p11;
            *(__half2*)&Psm[(wrow + gid)     * SKP + nt * 8 + 2 * tig] =
                __floats2half2_rn(p00, p01);
            *(__half2*)&Psm[(wrow + gid + 8) * SKP + nt * 8 + 2 * tig] =
                __floats2half2_rn(p10, p11);
        }
        sum0 += __shfl_xor_sync(0xffffffffu, sum0, 1);
        sum0 += __shfl_xor_sync(0xffffffffu, sum0, 2);
        sum1 += __shfl_xor_sync(0xffffffffu, sum1, 1);
        sum1 += __shfl_xor_sync(0xffffffffu, sum1, 2);

        const float a0 = __expf(mrow0 - nm0);
        const float a1 = __expf(mrow1 - nm1);
        lrow0 = lrow0 * a0 + sum0;
        lrow1 = lrow1 * a1 + sum1;
        mrow0 = nm0; mrow1 = nm1;
#pragma unroll
        for (int nt = 0; nt < 8; nt++) {
            Oacc[nt][0] *= a0; Oacc[nt][1] *= a0;
            Oacc[nt][2] *= a1; Oacc[nt][3] *= a1;
        }
        __syncwarp();

        // ---- O += P @ V  (4 k16-steps over keys; V via ldmatrix.trans) ----
#pragma unroll
        for (int kk = 0; kk < 4; kk++) {
            uint32_t a0f, a1f, a2f, a3f;
            const uint32_t pa = psm0
                + (uint32_t)(wrow * (SKP * 2)) + kk * 32 + p_lane;
            ldsm_x4(a0f, a1f, a2f, a3f, pa);
#pragma unroll
            for (int nt = 0; nt < 8; nt++) {
                uint32_t b0, b1;
                const uint32_t va = vst
                    + (uint32_t)(kk * 16 * (SV * 2)) + nt * 16 + v_lane;
                ldsm_x2_trans(b0, b1, va);
                mma_f16(Oacc[nt], a0f, a1f, a2f, a3f, b0, b1);
            }
        }
        __syncthreads();
    }

    const float i0 = 1.0f / lrow0;
    const float i1 = 1.0f / lrow1;
    const int r0g = qbase + wrow + gid;
#pragma unroll
    for (int nt = 0; nt < 8; nt++) {
        const int c = h * HDIM + nt * 8 + 2 * tig;
        *(__half2*)&g_attn16[((size_t)b * T_SEQ + r0g)     * DM + c] =
            __floats2half2_rn(Oacc[nt][0] * i0, Oacc[nt][1] * i0);
        *(__half2*)&g_attn16[((size_t)b * T_SEQ + r0g + 8) * DM + c] =
            __floats2half2_rn(Oacc[nt][2] * i1, Oacc[nt][3] * i1);
    }
}

// ===========================================================================
extern "C" void kernel_launch(void* const* d_in, const int* in_sizes, int n_in,
                              void* d_out, int out_size)
{
    const float* x    = (const float*)d_in[0];
    const float* Wqkv = (const float*)d_in[1];
    const float* Wout = (const float*)d_in[2];
    float* out = (float*)d_out;

    __half *attn16 = nullptr, *wqkvT = nullptr, *woutT = nullptr, *x16 = nullptr;
    cudaGetSymbolAddress((void**)&attn16, g_attn16);
    cudaGetSymbolAddress((void**)&wqkvT,  g_WqkvT16);
    cudaGetSymbolAddress((void**)&woutT,  g_WoutT16);
    cudaGetSymbolAddress((void**)&x16,    g_x16);

    cudaFuncSetAttribute(gemm_qkv_fused,
                         cudaFuncAttributeMaxDynamicSharedMemorySize, GEMM_SMEM);
    cudaFuncSetAttribute(gemm_f16,
                         cudaFuncAttributeMaxDynamicSharedMemorySize, GEMM_SMEM);
    cudaFuncSetAttribute(flash_attn_tc,
                         cudaFuncAttributeMaxDynamicSharedMemorySize, FA_SMEM);

    // 0) RoPE table, weight transposes (+fp16 round), x round
    rope_table_kernel<<<(T_SEQ * 32 + 255) / 256, 256>>>();
    transpose_f16_kernel<<<dim3(QKV_COLS / 32, DM / 32), dim3(32, 8)>>>(
        Wqkv, wqkvT, DM, QKV_COLS);
    transpose_f16_kernel<<<dim3(DM / 32, DM / 32), dim3(32, 8)>>>(
        Wout, woutT, DM, DM);
    convert_x_kernel<<<(ROWS * DM / 4) / 256, 256>>>(x);

    // 1) QKV projection (fp16 mma) + fused RoPE + per-head pack
    gemm_qkv_fused<<<dim3(QKV_COLS / 128, ROWS / 128), 256, GEMM_SMEM>>>(
        x16, wqkvT, DM);

    // 2) Causal flash attention (fp16 mma, 128-row CTAs)
    flash_attn_tc<<<dim3(T_SEQ / 128, NHEAD, B_BATCH), 256, FA_SMEM>>>();

    // 3) Output projection (fp16 mma, fp32 out)
    gemm_f16<<<dim3(DM / 128, ROWS / 128), 256, GEMM_SMEM>>>(
        attn16, woutT, out, DM, DM);
}

// round 15
// speedup vs baseline: 1.9583x; 1.0063x over previous
#include <cuda_runtime.h>
#include <cuda_fp16.h>
#include <cstdint>
#include <math.h>

#define T_SEQ    2048
#define B_BATCH  2
#define DM       1024
#define NHEAD    16
#define HDIM     64
#define ROWS     (B_BATCH * T_SEQ)      // 4096
#define QKV_COLS (3 * DM)               // 3072

// Scratch (allocation-guard compliant: device globals) — all fp16
__device__ __half g_attn16[(size_t)ROWS * DM];          // 8 MB
__device__ __half g_x16[(size_t)ROWS * DM];             // 8 MB
__device__ __half g_WqkvT16[(size_t)QKV_COLS * DM];     // 6 MB [N][K]
__device__ __half g_WoutT16[(size_t)DM * DM];           // 2 MB [N][K]
__device__ float  g_rope_tab[(size_t)T_SEQ * 32 * 2];   // 512 KB (sin,cos)
// Packed per-head fp16 tensors [b][h][t][64]
__device__ __half g_qpk[(size_t)ROWS * DM];             // 8 MB (q * 1/8)
__device__ __half g_kpk[(size_t)ROWS * DM];             // 8 MB
__device__ __half g_vpk[(size_t)ROWS * DM];             // 8 MB

__device__ __forceinline__ uint32_t smem_u32(const void* p) {
    uint32_t a;
    asm("{ .reg .u64 t; cvta.to.shared.u64 t, %1; cvt.u32.u64 %0, t; }"
        : "=r"(a) : "l"(p));
    return a;
}
__device__ __forceinline__ void cp16(uint32_t dst, const void* src) {
    asm volatile("cp.async.cg.shared.global [%0], [%1], 16;"
                 :: "r"(dst), "l"(src));
}
#define CP_COMMIT() asm volatile("cp.async.commit_group;" ::: "memory")
#define CP_WAIT2()  asm volatile("cp.async.wait_group 2;" ::: "memory")
#define CP_WAIT1()  asm volatile("cp.async.wait_group 1;" ::: "memory")
#define CP_WAIT0()  asm volatile("cp.async.wait_group 0;" ::: "memory")

__device__ __forceinline__ void mma_f16(
    float* c, uint32_t a0, uint32_t a1, uint32_t a2, uint32_t a3,
    uint32_t b0, uint32_t b1)
{
    asm volatile(
        "mma.sync.aligned.m16n8k16.row.col.f32.f16.f16.f32 "
        "{%0,%1,%2,%3}, {%4,%5,%6,%7}, {%8,%9}, {%0,%1,%2,%3};"
        : "+f"(c[0]), "+f"(c[1]), "+f"(c[2]), "+f"(c[3])
        : "r"(a0), "r"(a1), "r"(a2), "r"(a3), "r"(b0), "r"(b1));
}
__device__ __forceinline__ void ldsm_x4(
    uint32_t& r0, uint32_t& r1, uint32_t& r2, uint32_t& r3, uint32_t addr)
{
    asm volatile("ldmatrix.sync.aligned.m8n8.x4.shared.b16 {%0,%1,%2,%3}, [%4];"
                 : "=r"(r0), "=r"(r1), "=r"(r2), "=r"(r3) : "r"(addr));
}
__device__ __forceinline__ void ldsm_x4_trans(
    uint32_t& r0, uint32_t& r1, uint32_t& r2, uint32_t& r3, uint32_t addr)
{
    asm volatile("ldmatrix.sync.aligned.m8n8.x4.trans.shared.b16 {%0,%1,%2,%3}, [%4];"
                 : "=r"(r0), "=r"(r1), "=r"(r2), "=r"(r3) : "r"(addr));
}

// ===========================================================================
// Transpose + fp16 round: src [R][C] fp32 -> dst [C][R] fp16
// ===========================================================================
__global__ void transpose_f16_kernel(const float* __restrict__ src,
                                     __half* __restrict__ dst, int R, int C)
{
    __shared__ float tile[32][33];
    int c0 = blockIdx.x * 32, r0 = blockIdx.y * 32;
    int x = threadIdx.x, y = threadIdx.y;   // 32 x 8
#pragma unroll
    for (int i = 0; i < 32; i += 8)
        tile[y + i][x] = src[(size_t)(r0 + y + i) * C + c0 + x];
    __syncthreads();
#pragma unroll
    for (int i = 0; i < 32; i += 8)
        dst[(size_t)(c0 + y + i) * R + r0 + x] = __float2half_rn(tile[x][y + i]);
}

// x -> fp16 copy
__global__ void convert_x_kernel(const float* __restrict__ x)
{
    int i = blockIdx.x * blockDim.x + threadIdx.x;
    float4 v = *(const float4*)(x + 4 * (size_t)i);
    __half2 h0 = __floats2half2_rn(v.x, v.y);
    __half2 h1 = __floats2half2_rn(v.z, v.w);
    *(__half2*)&g_x16[4 * (size_t)i]     = h0;
    *(__half2*)&g_x16[4 * (size_t)i + 2] = h1;
}

// ===========================================================================
// RoPE table
// ===========================================================================
__global__ void rope_table_kernel()
{
    int idx = blockIdx.x * blockDim.x + threadIdx.x;   // 65536
    if (idx >= T_SEQ * 32) return;
    int i = idx & 31;
    int t = idx >> 5;
    double ang = (double)t * pow(10000.0, -(double)i / 32.0);
    g_rope_tab[2 * idx + 0] = (float)sin(ang);
    g_rope_tab[2 * idx + 1] = (float)cos(ang);
}

// ===========================================================================
// fp16 GEMM mainloop: 128x128 tile, BK=32 halves, 4-stage cp.async,
// all-x4 ldmatrix frags, m16n8k16 fp16 mma w/ fp32 accum. Stride 40 halves.
// ===========================================================================
#define SSTH 40
#define NSTG 4
#define STG_HALVES (128 * SSTH)
#define GEMM_SMEM (NSTG * 2 * STG_HALVES * 2)   // 81920 B

__device__ __forceinline__ void gemm_mainloop_f16(
    const __half* __restrict__ A, const __half* __restrict__ Bt,
    int K, int bm, int bn, float acc[4][4][4], __half* sm)
{
    const int tid  = threadIdx.x;
    const int lane = tid & 31;
    const int wid  = tid >> 5;
    const int wm   = (wid >> 2) * 64;
    const int wn   = (wid & 3) * 32;

    __half* As = sm;
    __half* Bs = sm + NSTG * STG_HALVES;
    const uint32_t as0 = smem_u32(As);
    const uint32_t bs0 = smem_u32(Bs);
    const int r0 = tid >> 1;               // row 0..127
    const int c0 = (tid & 1) * 16;         // half offset

    const uint32_t a_lane = (uint32_t)((((lane >> 3) & 1) * 8 + (lane & 7)) * (SSTH * 2)
                                       + (lane >> 4) * 16);
    // B x4: lanes 0-7: nt rows/k-lo, 8-15: nt rows/k-hi, 16-23: nt+1 rows/k-lo,
    //       24-31: nt+1 rows/k-hi
    const uint32_t b_lane4 = (uint32_t)((lane & 7) * (SSTH * 2)
                                        + ((lane >> 3) & 1) * 16
                                        + (lane >> 4) * 8 * (SSTH * 2));

    auto issue = [&](int ch) {
        const int s  = ch & (NSTG - 1);
        const int k0 = ch << 5;            // halves
        const uint32_t ao = as0 + (uint32_t)(s * STG_HALVES + r0 * SSTH + c0) * 2;
        const uint32_t bo = bs0 + (uint32_t)(s * STG_HALVES + r0 * SSTH + c0) * 2;
        cp16(ao,      A  + (size_t)(bm + r0) * K + k0 + c0);
        cp16(ao + 16, A  + (size_t)(bm + r0) * K + k0 + c0 + 8);
        cp16(bo,      Bt + (size_t)(bn + r0) * K + k0 + c0);
        cp16(bo + 16, Bt + (size_t)(bn + r0) * K + k0 + c0 + 8);
        CP_COMMIT();
    };

    const int niter = K >> 5;              // BK = 32 halves
    issue(0); issue(1); issue(2);

    for (int it = 0; it < niter; it++) {
        CP_WAIT2();
        __syncthreads();
        if (it + 3 < niter) issue(it + 3);

        const uint32_t abase = as0 + (uint32_t)((it & (NSTG - 1)) * STG_HALVES) * 2;
        const uint32_t bbase = bs0 + (uint32_t)((it & (NSTG - 1)) * STG_HALVES) * 2;

#pragma unroll
        for (int ks = 0; ks < 2; ks++) {   // two k16 steps, +32B each
            uint32_t afr[4][4], bfr[4][2];
#pragma unroll
            for (int mt = 0; mt < 4; mt++) {
                const uint32_t ad = abase
                    + (uint32_t)((wm + mt * 16) * (SSTH * 2)) + ks * 32 + a_lane;
                ldsm_x4(afr[mt][0], afr[mt][1], afr[mt][2], afr[mt][3], ad);
            }
#pragma unroll
            for (int nt = 0; nt < 4; nt += 2) {
                const uint32_t bd = bbase
                    + (uint32_t)((wn + nt * 8) * (SSTH * 2)) + ks * 32 + b_lane4;
                ldsm_x4(bfr[nt][0], bfr[nt][1], bfr[nt + 1][0], bfr[nt + 1][1], bd);
            }
#pragma unroll
            for (int mt = 0; mt < 4; mt++)
#pragma unroll
                for (int nt = 0; nt < 4; nt++)
                    mma_f16(acc[mt][nt], afr[mt][0], afr[mt][1], afr[mt][2],
                            afr[mt][3], bfr[nt][0], bfr[nt][1]);
        }
    }
}

// ---------------------------------------------------------------------------
// QKV GEMM (fp16) with fused RoPE + per-head pack epilogue (fp16 outputs).
// ---------------------------------------------------------------------------
__global__ __launch_bounds__(256, 2) void gemm_qkv_fused(
    const __half* __restrict__ A, const __half* __restrict__ Bt, int K)
{
    extern __shared__ __half smh[];
    const int tid  = threadIdx.x;
    const int lane = tid & 31;
    const int wid  = tid >> 5;
    const int wm   = (wid >> 2) * 64;
    const int wn   = (wid & 3) * 32;
    const int bm   = blockIdx.y * 128;
    const int bn   = blockIdx.x * 128;
    const int gid  = lane >> 2;
    const int tig  = lane & 3;

    float acc[4][4][4];
#pragma unroll
    for (int i = 0; i < 4; i++)
#pragma unroll
        for (int j = 0; j < 4; j++)
#pragma unroll
            for (int q = 0; q < 4; q++) acc[i][j][q] = 0.0f;

    gemm_mainloop_f16(A, Bt, K, bm, bn, acc, smh);

#pragma unroll
    for (int mt = 0; mt < 4; mt++) {
        const int rb = bm + wm + mt * 16 + gid;
#pragma unroll
        for (int nt = 0; nt < 4; nt++) {
            const int c  = bn + wn + nt * 8 + 2 * tig;
            const int region = c >> 10;
            const int cc = c & 1023;
            const int h  = cc >> 6;
            const int d  = cc & 63;
            const int i2 = d >> 1;
#pragma unroll
            for (int half = 0; half < 2; half++) {
                const int r = rb + half * 8;
                const int t = r & (T_SEQ - 1);
                const int b = r >> 11;
                const float a0 = acc[mt][nt][2 * half + 0];
                const float a1 = acc[mt][nt][2 * half + 1];
                const size_t dst =
                    ((size_t)(b * NHEAD + h) * T_SEQ + t) * HDIM + d;
                if (region == 2) {
                    *(__half2*)&g_vpk[dst] = __floats2half2_rn(a0, a1);
                } else {
                    const float sn = g_rope_tab[2 * (t * 32 + i2) + 0];
                    const float cs = g_rope_tab[2 * (t * 32 + i2) + 1];
                    float o0 = a0 * cs - a1 * sn;
                    float o1 = a1 * cs + a0 * sn;
                    if (region == 0) {
                        *(__half2*)&g_qpk[dst] =
                            __floats2half2_rn(o0 * 0.125f, o1 * 0.125f);
                    } else {
                        *(__half2*)&g_kpk[dst] = __floats2half2_rn(o0, o1);
                    }
                }
            }
        }
    }
}

// ---------------------------------------------------------------------------
// Plain fp16 GEMM, fp32 output (output projection)
// ---------------------------------------------------------------------------
__global__ __launch_bounds__(256, 2) void gemm_f16(
    const __half* __restrict__ A, const __half* __restrict__ Bt,
    float* __restrict__ C, int N, int K)
{
    extern __shared__ __half smh[];
    const int tid  = threadIdx.x;
    const int lane = tid & 31;
    const int wid  = tid >> 5;
    const int wm   = (wid >> 2) * 64;
    const int wn   = (wid & 3) * 32;
    const int bm   = blockIdx.y * 128;
    const int bn   = blockIdx.x * 128;
    const int gid  = lane >> 2;
    const int tig  = lane & 3;

    float acc[4][4][4];
#pragma unroll
    for (int i = 0; i < 4; i++)
#pragma unroll
        for (int j = 0; j < 4; j++)
#pragma unroll
            for (int q = 0; q < 4; q++) acc[i][j][q] = 0.0f;

    gemm_mainloop_f16(A, Bt, K, bm, bn, acc, smh);

#pragma unroll
    for (int mt = 0; mt < 4; mt++) {
        const int rb = bm + wm + mt * 16;
#pragma unroll
        for (int nt = 0; nt < 4; nt++) {
            const int cb = bn + wn + nt * 8 + 2 * tig;
            float2 lo = {acc[mt][nt][0], acc[mt][nt][1]};
            float2 hi = {acc[mt][nt][2], acc[mt][nt][3]};
            *(float2*)(C + (size_t)(rb + gid)     * N + cb) = lo;
            *(float2*)(C + (size_t)(rb + gid + 8) * N + cb) = hi;
        }
    }
}

// ===========================================================================
// fp16 tensor-core causal flash attention (128 q-rows, 8 warps, 2 CTAs/SM).
// Strides 72 halves (144B). All fragments via ldmatrix.x4 (nt-pairs merged).
// ===========================================================================
#define SKP 72
#define SV  72
#define FA_SMEM ((2 * 64 * SKP + 2 * 64 * SV + 128 * SKP) * 2)   // 55296 B

__global__ __launch_bounds__(256) void flash_attn_tc()
{
    extern __shared__ __half smh[];
    __half* Ksm = smh;                       // [2][key][d]  stride 72
    __half* Vsm = Ksm + 2 * 64 * SKP;        // [2][key][d]  stride 72
    __half* Psm = Vsm + 2 * 64 * SV;         // [m][key]     stride 72

    const int tid  = threadIdx.x;
    const int lane = tid & 31;
    const int wid  = tid >> 5;
    const int gid  = lane >> 2;
    const int tig  = lane & 3;
    const int qi = (int)(gridDim.x - 1 - blockIdx.x);
    const int h = blockIdx.y, b = blockIdx.z;
    const int qbase = qi * 128;
    const int bh = b * NHEAD + h;
    const int wrow = 16 * wid;

    const uint32_t ksm0 = smem_u32(Ksm);
    const uint32_t vsm0 = smem_u32(Vsm);
    const uint32_t psm0 = smem_u32(Psm);
    const __half* kbase_p = g_kpk + (size_t)bh * T_SEQ * HDIM;
    const __half* vbase_p = g_vpk + (size_t)bh * T_SEQ * HDIM;

    // ldmatrix lane byte offsets
    // K x4 (nt pair): lanes 0-7 nt/k-lo, 8-15 nt/k-hi, 16-23 nt+1/k-lo, 24-31 nt+1/k-hi
    const uint32_t k_lane4 = (uint32_t)((lane & 7) * (SKP * 2)
                                        + ((lane >> 3) & 1) * 16
                                        + (lane >> 4) * 8 * (SKP * 2));
    const uint32_t p_lane = (uint32_t)((((lane >> 3) & 1) * 8 + (lane & 7)) * (SKP * 2)
                                       + (lane >> 4) * 16);
    // V x4 trans (nt pair): lanes 0-15 nt cols, 16-31 nt+1 cols
    const uint32_t v_lane4 = (uint32_t)((lane & 15) * (SV * 2)
                                        + (lane >> 4) * 16);

    auto issue_kv = [&](int kt, int st) {
        const int n = tid >> 2;                 // key 0..63
        const int q = (tid & 3) * 16;           // half offset (32B chunks)
        const size_t go = (size_t)(kt * 64 + n) * HDIM + q;
        const uint32_t ko = (uint32_t)(st * 64 * SKP + n * SKP + q) * 2;
        const uint32_t vo = (uint32_t)(st * 64 * SV  + n * SV  + q) * 2;
        cp16(ko + ksm0,      kbase_p + go);
        cp16(ko + ksm0 + 16, kbase_p + go + 8);
        cp16(vo + vsm0,      vbase_p + go);
        cp16(vo + vsm0 + 16, vbase_p + go + 8);
    };

    // stage Q (fp16, pre-scaled) into Psm: 256 threads cover 128 rows
    {
        int m = tid >> 1;
        int d0 = (tid & 1) * 32;
        const __half* src = g_qpk + ((size_t)bh * T_SEQ + qbase + m) * HDIM + d0;
#pragma unroll
        for (int j = 0; j < 4; j++) {
            uint4 v = *(const uint4*)(src + 8 * j);
            *(uint4*)&Psm[m * SKP + d0 + 8 * j] = v;
        }
    }

    const int nkt = qbase / 64 + 2;
    issue_kv(0, 0);
    CP_COMMIT();
    __syncthreads();

    // hoist Q fragments (4 k16-steps over d=64)
    uint32_t qf[4][4];
#pragma unroll
    for (int kp = 0; kp < 4; kp++) {
        const uint32_t qa = psm0 + (uint32_t)(wrow * (SKP * 2)) + kp * 32 + p_lane;
        ldsm_x4(qf[kp][0], qf[kp][1], qf[kp][2], qf[kp][3], qa);
    }

    float Oacc[8][4];
#pragma unroll
    for (int nt = 0; nt < 8; nt++)
#pragma unroll
        for (int q = 0; q < 4; q++) Oacc[nt][q] = 0.0f;
    float mrow0 = -1e30f, mrow1 = -1e30f, lrow0 = 0.0f, lrow1 = 0.0f;

    for (int kt = 0; kt < nkt; kt++) {
        const int st = kt & 1;
        const int kb = kt * 64;
        const bool more = (kt + 1) < nkt;
        if (more) { issue_kv(kt + 1, st ^ 1); CP_COMMIT(); }
        if (more) { CP_WAIT1(); } else { CP_WAIT0(); }
        __syncthreads();

        const uint32_t kst = ksm0 + (uint32_t)(st * 64 * SKP * 2);
        const uint32_t vst = vsm0 + (uint32_t)(st * 64 * SV * 2);

        // ---- S = Q @ K^T  (K frags x4, nt-pairs) ----
        float sacc[8][4];
#pragma unroll
        for (int nt = 0; nt < 8; nt++)
#pragma unroll
            for (int q = 0; q < 4; q++) sacc[nt][q] = 0.0f;

#pragma unroll
        for (int kp = 0; kp < 4; kp++) {
#pragma unroll
            for (int nt = 0; nt < 8; nt += 2) {
                uint32_t b0, b1, b2, b3;
                const uint32_t ka = kst
                    + (uint32_t)(nt * 8 * (SKP * 2)) + kp * 32 + k_lane4;
                ldsm_x4(b0, b1, b2, b3, ka);
                mma_f16(sacc[nt],     qf[kp][0], qf[kp][1], qf[kp][2], qf[kp][3],
                        b0, b1);
                mma_f16(sacc[nt + 1], qf[kp][0], qf[kp][1], qf[kp][2], qf[kp][3],
                        b2, b3);
            }
        }

        // ---- causal mask (last two tiles only) ----
        const int r0g = qbase + wrow + gid;
        if (kb + 63 > qbase) {
#pragma unroll
            for (int nt = 0; nt < 8; nt++) {
                int col = kb + nt * 8 + 2 * tig;
                if (col     > r0g)     sacc[nt][0] = -1e30f;
                if (col + 1 > r0g)     sacc[nt][1] = -1e30f;
                if (col     > r0g + 8) sacc[nt][2] = -1e30f;
                if (col + 1 > r0g + 8) sacc[nt][3] = -1e30f;
            }
        }

        // ---- online softmax ----
        float mx0 = -1e30f, mx1 = -1e30f;
#pragma unroll
        for (int nt = 0; nt < 8; nt++) {
            mx0 = fmaxf(mx0, fmaxf(sacc[nt][0], sacc[nt][1]));
            mx1 = fmaxf(mx1, fmaxf(sacc[nt][2], sacc[nt][3]));
        }
        mx0 = fmaxf(mx0, __shfl_xor_sync(0xffffffffu, mx0, 1));
        mx0 = fmaxf(mx0, __shfl_xor_sync(0xffffffffu, mx0, 2));
        mx1 = fmaxf(mx1, __shfl_xor_sync(0xffffffffu, mx1, 1));
        mx1 = fmaxf(mx1, __shfl_xor_sync(0xffffffffu, mx1, 2));
        const float nm0 = fmaxf(mrow0, mx0);
        const float nm1 = fmaxf(mrow1, mx1);

        float sum0 = 0.0f, sum1 = 0.0f;
#pragma unroll
        for (int nt = 0; nt < 8; nt++) {
            float p00 = __expf(sacc[nt][0] - nm0);
            float p01 = __expf(sacc[nt][1] - nm0);
            float p10 = __expf(sacc[nt][2] - nm1);
            float p11 = __expf(sacc[nt][3] - nm1);
            sum0 += p00 + p01;
            sum1 += p10 + p11;
            *(__half2*)&Psm[(wrow + gid)     * SKP + nt * 8 + 2 * tig] =
                __floats2half2_rn(p00, p01);
            *(__half2*)&Psm[(wrow + gid + 8) * SKP + nt * 8 + 2 * tig] =
                __floats2half2_rn(p10, p11);
        }
        sum0 += __shfl_xor_sync(0xffffffffu, sum0, 1);
        sum0 += __shfl_xor_sync(0xffffffffu, sum0, 2);
        sum1 += __shfl_xor_sync(0xffffffffu, sum1, 1);
        sum1 += __shfl_xor_sync(0xffffffffu, sum1, 2);

        const float a0 = __expf(mrow0 - nm0);
        const float a1 = __expf(mrow1 - nm1);
        lrow0 = lrow0 * a0 + sum0;
        lrow1 = lrow1 * a1 + sum1;
        mrow0 = nm0; mrow1 = nm1;
#pragma unroll
        for (int nt = 0; nt < 8; nt++) {
            Oacc[nt][0] *= a0; Oacc[nt][1] *= a0;
            Oacc[nt][2] *= a1; Oacc[nt][3] *= a1;
        }
        __syncwarp();

        // ---- O += P @ V  (V frags x4.trans, nt-pairs) ----
#pragma unroll
        for (int kk = 0; kk < 4; kk++) {
            uint32_t a0f, a1f, a2f, a3f;
            const uint32_t pa = psm0
                + (uint32_t)(wrow * (SKP * 2)) + kk * 32 + p_lane;
            ldsm_x4(a0f, a1f, a2f, a3f, pa);
#pragma unroll
            for (int nt = 0; nt < 8; nt += 2) {
                uint32_t b0, b1, b2, b3;
                const uint32_t va = vst
                    + (uint32_t)(kk * 16 * (SV * 2)) + nt * 16 + v_lane4;
                ldsm_x4_trans(b0, b1, b2, b3, va);
                mma_f16(Oacc[nt],     a0f, a1f, a2f, a3f, b0, b1);
                mma_f16(Oacc[nt + 1], a0f, a1f, a2f, a3f, b2, b3);
            }
        }
        __syncthreads();
    }

    const float i0 = 1.0f / lrow0;
    const float i1 = 1.0f / lrow1;
    const int r0g = qbase + wrow + gid;
#pragma unroll
    for (int nt = 0; nt < 8; nt++) {
        const int c = h * HDIM + nt * 8 + 2 * tig;
        *(__half2*)&g_attn16[((size_t)b * T_SEQ + r0g)     * DM + c] =
            __floats2half2_rn(Oacc[nt][0] * i0, Oacc[nt][1] * i0);
        *(__half2*)&g_attn16[((size_t)b * T_SEQ + r0g + 8) * DM + c] =
            __floats2half2_rn(Oacc[nt][2] * i1, Oacc[nt][3] * i1);
    }
}

// ===========================================================================
extern "C" void kernel_launch(void* const* d_in, const int* in_sizes, int n_in,
                              void* d_out, int out_size)
{
    const float* x    = (const float*)d_in[0];
    const float* Wqkv = (const float*)d_in[1];
    const float* Wout = (const float*)d_in[2];
    float* out = (float*)d_out;

    __half *attn16 = nullptr, *wqkvT = nullptr, *woutT = nullptr, *x16 = nullptr;
    cudaGetSymbolAddress((void**)&attn16, g_attn16);
    cudaGetSymbolAddress((void**)&wqkvT,  g_WqkvT16);
    cudaGetSymbolAddress((void**)&woutT,  g_WoutT16);
    cudaGetSymbolAddress((void**)&x16,    g_x16);

    cudaFuncSetAttribute(gemm_qkv_fused,
                         cudaFuncAttributeMaxDynamicSharedMemorySize, GEMM_SMEM);
    cudaFuncSetAttribute(gemm_f16,
                         cudaFuncAttributeMaxDynamicSharedMemorySize, GEMM_SMEM);
    cudaFuncSetAttribute(flash_attn_tc,
                         cudaFuncAttributeMaxDynamicSharedMemorySize, FA_SMEM);

    // 0) RoPE table, weight transposes (+fp16 round), x round
    rope_table_kernel<<<(T_SEQ * 32 + 255) / 256, 256>>>();
    transpose_f16_kernel<<<dim3(QKV_COLS / 32, DM / 32), dim3(32, 8)>>>(
        Wqkv, wqkvT, DM, QKV_COLS);
    transpose_f16_kernel<<<dim3(DM / 32, DM / 32), dim3(32, 8)>>>(
        Wout, woutT, DM, DM);
    convert_x_kernel<<<(ROWS * DM / 4) / 256, 256>>>(x);

    // 1) QKV projection (fp16 mma) + fused RoPE + per-head pack
    gemm_qkv_fused<<<dim3(QKV_COLS / 128, ROWS / 128), 256, GEMM_SMEM>>>(
        x16, wqkvT, DM);

    // 2) Causal flash attention (fp16 mma, 128-row CTAs)
    flash_attn_tc<<<dim3(T_SEQ / 128, NHEAD, B_BATCH), 256, FA_SMEM>>>();

    // 3) Output projection (fp16 mma, fp32 out)
    gemm_f16<<<dim3(DM / 128, ROWS / 128), 256, GEMM_SMEM>>>(
        attn16, woutT, out, DM, DM);
}